// round 11
// baseline (speedup 1.0000x reference)
#include <cuda_runtime.h>
#include <cuda_bf16.h>
#include <cuda_fp16.h>
#include <math.h>
#include <stdint.h>

#define Bb 4
#define Ls 2048
#define Es 512
#define Hh 8
#define Dd 64
#define Uu 40
#define NTOP 40
#define BH (Bb*Hh)

// ---------------- scratch (device globals; no allocations allowed) ----------------
__device__ float g_q[Bb*Ls*Es];              // fp32 projected q [b][l][e], e=h*64+d
__device__ float g_k[Bb*Ls*Es];
__device__ float g_v[Bb*Ls*Es];
__device__ __nv_bfloat16 g_abf[2*Bb*Ls*1024];  // [proj(q,k)][row][0:512]=hi,[512:1024]=lo
__device__ __nv_bfloat16 g_wbf[2*Es*1024];
__device__ __half g_vhf[Bb*Ls*Es];             // fp16 value input
__device__ __half g_wvhf[Es*Es];               // fp16 Wv
__device__ float g_cmean[Bb*Es];               // column mean of value input
__device__ float g_M[BH*Ls];
__device__ int   g_top[BH*NTOP];
__device__ float g_scores[BH*NTOP*Ls];
__device__ float g_upd[BH*NTOP*Dd];
__device__ float g_vmean[BH*Dd];
__device__ float g_base[Bb*Es];

// ================= helpers =================
__device__ __forceinline__ uint32_t smem_u32(const void* p) {
    uint32_t a;
    asm("{ .reg .u64 t; cvta.to.shared.u64 t, %1; cvt.u32.u64 %0, t; }" : "=r"(a) : "l"(p));
    return a;
}

__device__ __forceinline__ void cpa16(uint32_t s, const void* g) {
    asm volatile("cp.async.cg.shared.global [%0], [%1], 16;" :: "r"(s), "l"(g));
}
#define CPA_COMMIT() asm volatile("cp.async.commit_group;" ::: "memory")
#define CPA_WAIT(n)  asm volatile("cp.async.wait_group %0;" :: "n"(n) : "memory")

#define LDSM_X4(r, addr) \
    asm volatile("ldmatrix.sync.aligned.m8n8.x4.shared.b16 {%0,%1,%2,%3}, [%4];" \
        : "=r"((r)[0]), "=r"((r)[1]), "=r"((r)[2]), "=r"((r)[3]) : "r"(addr))
#define LDSM_X2(r, addr) \
    asm volatile("ldmatrix.sync.aligned.m8n8.x2.shared.b16 {%0,%1}, [%2];" \
        : "=r"((r)[0]), "=r"((r)[1]) : "r"(addr))

__device__ __forceinline__ void mma16816(float* d, const uint32_t* a, const uint32_t* b) {
    asm volatile(
        "mma.sync.aligned.m16n8k16.row.col.f32.bf16.bf16.f32 "
        "{%0,%1,%2,%3}, {%4,%5,%6,%7}, {%8,%9}, {%0,%1,%2,%3};"
        : "+f"(d[0]), "+f"(d[1]), "+f"(d[2]), "+f"(d[3])
        : "r"(a[0]), "r"(a[1]), "r"(a[2]), "r"(a[3]), "r"(b[0]), "r"(b[1]));
}
__device__ __forceinline__ void mma16816h(float* d, const uint32_t* a, const uint32_t* b) {
    asm volatile(
        "mma.sync.aligned.m16n8k16.row.col.f32.f16.f16.f32 "
        "{%0,%1,%2,%3}, {%4,%5,%6,%7}, {%8,%9}, {%0,%1,%2,%3};"
        : "+f"(d[0]), "+f"(d[1]), "+f"(d[2]), "+f"(d[3])
        : "r"(a[0]), "r"(a[1]), "r"(a[2]), "r"(a[3]), "r"(b[0]), "r"(b[1]));
}

// ================= 0) conversions =================
__device__ __forceinline__ void split4(float4 x, __nv_bfloat16* hi, __nv_bfloat16* lo) {
    float xs[4] = {x.x, x.y, x.z, x.w};
    #pragma unroll
    for (int i = 0; i < 4; i++) {
        __nv_bfloat16 h = __float2bfloat16_rn(xs[i]);
        hi[i] = h;
        lo[i] = __float2bfloat16_rn(xs[i] - __bfloat162float(h));
    }
}

__global__ void __launch_bounds__(256) cvt_inputs(const float* __restrict__ q,
                                                  const float* __restrict__ k,
                                                  const float* __restrict__ v) {
    int p = blockIdx.z;
    int i = blockIdx.x * 256 + threadIdx.x;           // over 8192*512/4
    if (p == 2) {
        float4 x = ((const float4*)v)[i];
        __half h4[4];
        h4[0] = __float2half_rn(x.x); h4[1] = __float2half_rn(x.y);
        h4[2] = __float2half_rn(x.z); h4[3] = __float2half_rn(x.w);
        int row = i >> 7, c4 = i & 127;
        *(uint2*)&g_vhf[(size_t)row * 512 + c4 * 4] = *(uint2*)h4;
        return;
    }
    const float* s = (p == 0) ? q : k;
    __nv_bfloat16* dst = g_abf + (size_t)p * Bb * Ls * 1024;
    float4 x = ((const float4*)s)[i];
    int row = i >> 7, c4 = i & 127;
    __nv_bfloat16 hi[4], lo[4];
    split4(x, hi, lo);
    *(uint2*)&dst[(size_t)row * 1024 + c4 * 4]       = *(uint2*)hi;
    *(uint2*)&dst[(size_t)row * 1024 + 512 + c4 * 4] = *(uint2*)lo;
}

__global__ void __launch_bounds__(256) cvt_weights(const float* __restrict__ wq,
                                                   const float* __restrict__ wk,
                                                   const float* __restrict__ wv) {
    int p = blockIdx.z;
    int i = blockIdx.x * 256 + threadIdx.x;           // over 512*512/4
    if (p == 0 && blockIdx.x == 0) {                  // zero g_cmean (runs before colmean)
        #pragma unroll
        for (int j = 0; j < 8; j++) g_cmean[j * 256 + threadIdx.x] = 0.f;
    }
    if (p == 2) {
        float4 x = ((const float4*)wv)[i];
        __half h4[4];
        h4[0] = __float2half_rn(x.x); h4[1] = __float2half_rn(x.y);
        h4[2] = __float2half_rn(x.z); h4[3] = __float2half_rn(x.w);
        int row = i >> 7, c4 = i & 127;
        *(uint2*)&g_wvhf[(size_t)row * 512 + c4 * 4] = *(uint2*)h4;
        return;
    }
    const float* s = (p == 0) ? wq : wk;
    __nv_bfloat16* dst = g_wbf + (size_t)p * Es * 1024;
    float4 x = ((const float4*)s)[i];
    int row = i >> 7, c4 = i & 127;
    __nv_bfloat16 hi[4], lo[4];
    split4(x, hi, lo);
    *(uint2*)&dst[(size_t)row * 1024 + c4 * 4]       = *(uint2*)hi;
    *(uint2*)&dst[(size_t)row * 1024 + 512 + c4 * 4] = *(uint2*)lo;
}

// ================= exact vmean: colmean(value) @ Wv^T + bv =================
__global__ void __launch_bounds__(256) colmean_kernel(const float* __restrict__ value) {
    int b = blockIdx.y, lc = blockIdx.x;               // 8 chunks of 256 rows
    int tid = threadIdx.x;
    const float* vb = value + ((size_t)b * Ls + (size_t)lc * 256) * Es;
    float s0 = 0.f, s1 = 0.f;
    for (int l = 0; l < 256; l++) {
        s0 += vb[(size_t)l * Es + tid];
        s1 += vb[(size_t)l * Es + 256 + tid];
    }
    atomicAdd(&g_cmean[b * Es + tid],       s0 * (1.0f / Ls));
    atomicAdd(&g_cmean[b * Es + 256 + tid], s1 * (1.0f / Ls));
}

__global__ void __launch_bounds__(256) vmean_gemm(const float* __restrict__ Wv,
                                                  const float* __restrict__ bv) {
    int b = blockIdx.x;
    __shared__ float cm[Es];
    int tid = threadIdx.x;
    cm[tid] = g_cmean[b * Es + tid];
    cm[tid + 256] = g_cmean[b * Es + 256 + tid];
    __syncthreads();
    for (int r = 0; r < 2; r++) {
        int e = r * 256 + tid;
        const float4* wr = (const float4*)(Wv + (size_t)e * Es);
        float acc = bv[e];
        for (int c4 = 0; c4 < Es / 4; c4++) {
            float4 w = wr[c4];
            acc += cm[4*c4] * w.x + cm[4*c4+1] * w.y + cm[4*c4+2] * w.z + cm[4*c4+3] * w.w;
        }
        g_vmean[b * Es + e] = acc;
    }
}

// ================= 1) mma.sync projection GEMMs =================
#define NCHUNK 24
#define CH_BYTES 16384          // 128 rows * 64 bf16 * 2B
#define SM_TOT (4*CH_BYTES)     // A0,B0,A1,B1

__device__ __forceinline__ void chunk_offs(int c, int& ak, int& bk) {
    int r = c & 7, s = c >> 3;
    ak = ((s == 2) ? 512 : 0) + r * 64;
    bk = ((s == 1) ? 512 : 0) + r * 64;
}

// swizzled smem byte offset: 128x64 b16 tile, 128B rows, XOR-by-row swizzle
__device__ __forceinline__ uint32_t tswz(int row, int c16) {
    return (uint32_t)(row * 128 + c16 * 16) ^ (uint32_t)((row & 7) << 4);
}

// q,k: split-bf16 3-term (AhBh + AhBl + AlBh), virtual K=1536
__global__ void __launch_bounds__(256, 2) proj_mma(const float* __restrict__ bq,
                                                   const float* __restrict__ bk_) {
    extern __shared__ char smem[];
    int z = blockIdx.z;
    int m0 = blockIdx.y * 128, n0 = blockIdx.x * 128;
    const __nv_bfloat16* Ab = g_abf + (size_t)z * Bb * Ls * 1024;
    const __nv_bfloat16* Wb = g_wbf + (size_t)z * Es * 1024;
    const float* bias = (z == 0) ? bq : bk_;
    float* C = (z == 0) ? g_q : g_k;

    uint32_t sb = smem_u32(smem);
    int tid = threadIdx.x, wid = tid >> 5, lane = tid & 31;
    uint32_t abuf[2] = { sb,            sb + 2 * CH_BYTES };
    uint32_t bbuf[2] = { sb + CH_BYTES, sb + 3 * CH_BYTES };

    int wm = (wid & 1) * 64;
    int wn = (wid >> 1) * 32;

    float acc[4][4][4];
    #pragma unroll
    for (int mi = 0; mi < 4; mi++)
        #pragma unroll
        for (int ni = 0; ni < 4; ni++)
            #pragma unroll
            for (int e = 0; e < 4; e++) acc[mi][ni][e] = 0.f;

    auto load_chunk = [&](int c, int p) {
        int ak, bk; chunk_offs(c, ak, bk);
        #pragma unroll
        for (int i = 0; i < 4; i++) {
            int j = tid + i * 256; int row = j >> 3, c16 = j & 7;
            cpa16(abuf[p] + tswz(row, c16), Ab + (size_t)(m0 + row) * 1024 + ak + c16 * 8);
        }
        #pragma unroll
        for (int i = 0; i < 4; i++) {
            int j = tid + i * 256; int row = j >> 3, c16 = j & 7;
            cpa16(bbuf[p] + tswz(row, c16), Wb + (size_t)(n0 + row) * 1024 + bk + c16 * 8);
        }
        CPA_COMMIT();
    };

    load_chunk(0, 0);
    load_chunk(1, 1);

    int lrow = lane & 15, lsel = lane >> 4;
    int brow = lane & 7,  bsel = (lane >> 3) & 1;

    for (int c = 0; c < NCHUNK; c++) {
        int p = c & 1;
        if (c + 1 < NCHUNK) { CPA_WAIT(1); } else { CPA_WAIT(0); }
        __syncthreads();
        #pragma unroll
        for (int ks = 0; ks < 4; ks++) {
            uint32_t af[4][4], bf[4][2];
            #pragma unroll
            for (int mi = 0; mi < 4; mi++) {
                uint32_t ad = abuf[p] + tswz(wm + mi * 16 + lrow, ks * 2 + lsel);
                LDSM_X4(af[mi], ad);
            }
            #pragma unroll
            for (int ni = 0; ni < 4; ni++) {
                uint32_t bd = bbuf[p] + tswz(wn + ni * 8 + brow, ks * 2 + bsel);
                LDSM_X2(bf[ni], bd);
            }
            #pragma unroll
            for (int mi = 0; mi < 4; mi++)
                #pragma unroll
                for (int ni = 0; ni < 4; ni++)
                    mma16816(acc[mi][ni], af[mi], bf[ni]);
        }
        __syncthreads();
        if (c + 2 < NCHUNK) load_chunk(c + 2, p);
    }

    int r0 = lane >> 2, cp2 = (lane & 3) * 2;
    #pragma unroll
    for (int ni = 0; ni < 4; ni++) {
        int col = n0 + wn + ni * 8 + cp2;
        float2 bv2 = *(const float2*)&bias[col];
        #pragma unroll
        for (int mi = 0; mi < 4; mi++) {
            int row = m0 + wm + mi * 16 + r0;
            float2 v0 = { acc[mi][ni][0] + bv2.x, acc[mi][ni][1] + bv2.y };
            float2 v1 = { acc[mi][ni][2] + bv2.x, acc[mi][ni][3] + bv2.y };
            *(float2*)&C[(size_t)row * 512 + col] = v0;
            *(float2*)&C[(size_t)(row + 8) * 512 + col] = v1;
        }
    }
}

// v: single-pass fp16, K=512
#define VCHUNK 8
__global__ void __launch_bounds__(256, 2) proj_v(const float* __restrict__ bv) {
    extern __shared__ char smem[];
    int m0 = blockIdx.y * 128, n0 = blockIdx.x * 128;
    uint32_t sb = smem_u32(smem);
    int tid = threadIdx.x, wid = tid >> 5, lane = tid & 31;
    uint32_t abuf[2] = { sb,            sb + 2 * CH_BYTES };
    uint32_t bbuf[2] = { sb + CH_BYTES, sb + 3 * CH_BYTES };
    int wm = (wid & 1) * 64, wn = (wid >> 1) * 32;

    float acc[4][4][4];
    #pragma unroll
    for (int mi = 0; mi < 4; mi++)
        #pragma unroll
        for (int ni = 0; ni < 4; ni++)
            #pragma unroll
            for (int e = 0; e < 4; e++) acc[mi][ni][e] = 0.f;

    auto load_chunk = [&](int c, int p) {
        int k0 = c * 64;
        #pragma unroll
        for (int i = 0; i < 4; i++) {
            int j = tid + i * 256; int row = j >> 3, c16 = j & 7;
            cpa16(abuf[p] + tswz(row, c16), g_vhf + (size_t)(m0 + row) * 512 + k0 + c16 * 8);
        }
        #pragma unroll
        for (int i = 0; i < 4; i++) {
            int j = tid + i * 256; int row = j >> 3, c16 = j & 7;
            cpa16(bbuf[p] + tswz(row, c16), g_wvhf + (size_t)(n0 + row) * 512 + k0 + c16 * 8);
        }
        CPA_COMMIT();
    };

    load_chunk(0, 0);
    load_chunk(1, 1);

    int lrow = lane & 15, lsel = lane >> 4;
    int brow = lane & 7,  bsel = (lane >> 3) & 1;

    for (int c = 0; c < VCHUNK; c++) {
        int p = c & 1;
        if (c + 1 < VCHUNK) { CPA_WAIT(1); } else { CPA_WAIT(0); }
        __syncthreads();
        #pragma unroll
        for (int ks = 0; ks < 4; ks++) {
            uint32_t af[4][4], bf[4][2];
            #pragma unroll
            for (int mi = 0; mi < 4; mi++) {
                uint32_t ad = abuf[p] + tswz(wm + mi * 16 + lrow, ks * 2 + lsel);
                LDSM_X4(af[mi], ad);
            }
            #pragma unroll
            for (int ni = 0; ni < 4; ni++) {
                uint32_t bd = bbuf[p] + tswz(wn + ni * 8 + brow, ks * 2 + bsel);
                LDSM_X2(bf[ni], bd);
            }
            #pragma unroll
            for (int mi = 0; mi < 4; mi++)
                #pragma unroll
                for (int ni = 0; ni < 4; ni++)
                    mma16816h(acc[mi][ni], af[mi], bf[ni]);
        }
        __syncthreads();
        if (c + 2 < VCHUNK) load_chunk(c + 2, p);
    }

    int r0 = lane >> 2, cp2 = (lane & 3) * 2;
    #pragma unroll
    for (int ni = 0; ni < 4; ni++) {
        int col = n0 + wn + ni * 8 + cp2;
        float2 bv2 = *(const float2*)&bv[col];
        #pragma unroll
        for (int mi = 0; mi < 4; mi++) {
            int row = m0 + wm + mi * 16 + r0;
            float2 v0 = { acc[mi][ni][0] + bv2.x, acc[mi][ni][1] + bv2.y };
            float2 v1 = { acc[mi][ni][2] + bv2.x, acc[mi][ni][3] + bv2.y };
            *(float2*)&g_v[(size_t)row * 512 + col] = v0;
            *(float2*)&g_v[(size_t)(row + 8) * 512 + col] = v1;
        }
    }
}

// ================= 3) M scoring (+ g_upd zeroing fold) =================
__global__ void __launch_bounds__(256) m_kernel(const int* __restrict__ idx) {
    // fold: zero g_upd (runs well before upd_kernel in stream order)
    if (blockIdx.y < 2) {
        int zid = (blockIdx.y * 256 + blockIdx.x) * 256 + threadIdx.x;
        if (zid < BH * NTOP * Dd) g_upd[zid] = 0.f;
    }
    int bh = blockIdx.y; int b = bh >> 3, h = bh & 7;
    int w = threadIdx.x >> 5, lane = threadIdx.x & 31;
    int l = blockIdx.x * 8 + w;
    int sg = lane >> 3, dg = lane & 7;
    const float* qrow = g_q + (size_t)(b * Ls + l) * Es + h * Dd + dg * 8;
    float4 q0 = *(const float4*)qrow;
    float4 q1 = *(const float4*)(qrow + 4);
    const int* irow = idx + l * Uu;
    const float* kb = g_k + (size_t)b * Ls * Es + h * Dd + dg * 8;
    float mx = -INFINITY, sm = 0.f;
    #pragma unroll
    for (int s0 = 0; s0 < Uu; s0 += 4) {
        int row = irow[s0 + sg];
        const float* kr = kb + (size_t)row * Es;
        float4 k0 = *(const float4*)kr;
        float4 k1 = *(const float4*)(kr + 4);
        float p = q0.x * k0.x + q0.y * k0.y + q0.z * k0.z + q0.w * k0.w
                + q1.x * k1.x + q1.y * k1.y + q1.z * k1.z + q1.w * k1.w;
        p += __shfl_down_sync(0xffffffffu, p, 4);
        p += __shfl_down_sync(0xffffffffu, p, 2);
        p += __shfl_down_sync(0xffffffffu, p, 1);
        if (dg == 0) { mx = fmaxf(mx, p); sm += p; }
    }
    mx = fmaxf(mx, __shfl_xor_sync(0xffffffffu, mx, 8));
    mx = fmaxf(mx, __shfl_xor_sync(0xffffffffu, mx, 16));
    sm += __shfl_xor_sync(0xffffffffu, sm, 8);
    sm += __shfl_xor_sync(0xffffffffu, sm, 16);
    if (lane == 0) g_M[bh * Ls + l] = mx - sm * (1.0f / Ls);
}

// ================= 4) top-40: register-resident, shuffle reductions =================
__global__ void __launch_bounds__(256) topk_kernel() {
    int bh = blockIdx.x;
    int tid = threadIdx.x, lane = tid & 31, wid = tid >> 5;
    float v[8];
    #pragma unroll
    for (int j = 0; j < 8; j++) v[j] = g_M[bh * Ls + j * 256 + tid];
    __shared__ float swv[8];
    __shared__ int swi[8];
    __shared__ int winner;
    for (int t = 0; t < NTOP; t++) {
        float best = -INFINITY; int bi = 1 << 30;
        #pragma unroll
        for (int j = 0; j < 8; j++) {
            int gi = j * 256 + tid;
            if (v[j] > best || (v[j] == best && gi < bi)) { best = v[j]; bi = gi; }
        }
        #pragma unroll
        for (int s = 16; s; s >>= 1) {
            float ov = __shfl_xor_sync(0xffffffffu, best, s);
            int   oi = __shfl_xor_sync(0xffffffffu, bi, s);
            if (ov > best || (ov == best && oi < bi)) { best = ov; bi = oi; }
        }
        if (lane == 0) { swv[wid] = best; swi[wid] = bi; }
        __syncthreads();
        if (tid == 0) {
            float bb = swv[0]; int ii = swi[0];
            #pragma unroll
            for (int w = 1; w < 8; w++)
                if (swv[w] > bb || (swv[w] == bb && swi[w] < ii)) { bb = swv[w]; ii = swi[w]; }
            winner = ii;
            g_top[bh * NTOP + t] = ii;
        }
        __syncthreads();
        int wi = winner;
        if ((wi & 255) == tid) v[wi >> 8] = -INFINITY;
    }
}

// ================= 5) scores =================
__global__ void __launch_bounds__(256) scores_kernel() {
    int bh = blockIdx.y; int b = bh / Hh, h = bh % Hh;
    int jt = blockIdx.x;
    __shared__ float qs[NTOP][Dd];
    __shared__ float ks[128][65];
    __shared__ int ti[NTOP];
    int tid = threadIdx.x;
    if (tid < NTOP) ti[tid] = g_top[bh * NTOP + tid];
    __syncthreads();
    for (int i = tid; i < NTOP * Dd; i += 256) {
        int u = i >> 6, d = i & 63;
        qs[u][d] = g_q[(size_t)(b * Ls + ti[u]) * Es + h * Dd + d];
    }
    const float* kb = g_k + (size_t)b * Ls * Es + (size_t)jt * 128 * Es + h * Dd;
    for (int i = tid; i < 128 * Dd; i += 256) {
        int j = i >> 6, d = i & 63;
        ks[j][d] = kb[(size_t)j * Es + d];
    }
    __syncthreads();
    int tu = tid >> 5, tj = tid & 31;
    float acc[5][4];
    #pragma unroll
    for (int i = 0; i < 5; i++)
        #pragma unroll
        for (int jj = 0; jj < 4; jj++) acc[i][jj] = 0.f;
    for (int d = 0; d < Dd; d++) {
        float a[5], kv[4];
        #pragma unroll
        for (int i = 0; i < 5; i++) a[i] = qs[tu * 5 + i][d];
        #pragma unroll
        for (int jj = 0; jj < 4; jj++) kv[jj] = ks[tj + 32 * jj][d];
        #pragma unroll
        for (int i = 0; i < 5; i++)
            #pragma unroll
            for (int jj = 0; jj < 4; jj++) acc[i][jj] = fmaf(a[i], kv[jj], acc[i][jj]);
    }
    #pragma unroll
    for (int i = 0; i < 5; i++)
        #pragma unroll
        for (int jj = 0; jj < 4; jj++) {
            int u = tu * 5 + i, j = jt * 128 + tj + 32 * jj;
            g_scores[(size_t)(bh * NTOP + u) * Ls + j] = acc[i][jj];
        }
}

// ================= 6) softmax (register-cached, single global read) =================
__global__ void __launch_bounds__(256) softmax_kernel() {
    int row = blockIdx.x;
    float* p = g_scores + (size_t)row * Ls;
    int tid = threadIdx.x, lane = tid & 31, wid = tid >> 5;
    __shared__ float red[8];
    float x[8];
    #pragma unroll
    for (int j = 0; j < 8; j++) x[j] = p[j * 256 + tid];
    float mx = x[0];
    #pragma unroll
    for (int j = 1; j < 8; j++) mx = fmaxf(mx, x[j]);
    #pragma unroll
    for (int s = 16; s; s >>= 1) mx = fmaxf(mx, __shfl_xor_sync(0xffffffffu, mx, s));
    if (lane == 0) red[wid] = mx;
    __syncthreads();
    mx = red[0];
    #pragma unroll
    for (int w = 1; w < 8; w++) mx = fmaxf(mx, red[w]);
    float sm = 0.f;
    #pragma unroll
    for (int j = 0; j < 8; j++) { x[j] = __expf(x[j] - mx); sm += x[j]; }
    #pragma unroll
    for (int s = 16; s; s >>= 1) sm += __shfl_xor_sync(0xffffffffu, sm, s);
    __syncthreads();
    if (lane == 0) red[wid] = sm;
    __syncthreads();
    sm = 0.f;
    #pragma unroll
    for (int w = 0; w < 8; w++) sm += red[w];
    float inv = 1.0f / sm;
    #pragma unroll
    for (int j = 0; j < 8; j++) p[j * 256 + tid] = x[j] * inv;
}

// ================= 7) upd = attn @ v =================
__global__ void __launch_bounds__(256) upd_kernel() {
    int bh = blockIdx.y; int b = bh / Hh, h = bh % Hh;
    int jc = blockIdx.x;
    __shared__ float vs[64][65];
    __shared__ float as[NTOP][64];
    int tid = threadIdx.x;
    int td = tid & 63, tg = tid >> 6;
    float acc[10];
    #pragma unroll
    for (int i = 0; i < 10; i++) acc[i] = 0.f;
    for (int jt = 0; jt < 4; jt++) {
        int j0 = jc * 256 + jt * 64;
        const float* vb = g_v + (size_t)b * Ls * Es + (size_t)j0 * Es + h * Dd;
        for (int i = tid; i < 64 * 64; i += 256) { int j = i >> 6, d = i & 63; vs[j][d] = vb[(size_t)j * Es + d]; }
        for (int i = tid; i < NTOP * 64; i += 256) { int u = i >> 6, j = i & 63; as[u][j] = g_scores[(size_t)(bh * NTOP + u) * Ls + j0 + j]; }
        __syncthreads();
        for (int jj = 0; jj < 64; jj++) {
            float vv = vs[jj][td];
            #pragma unroll
            for (int i = 0; i < 10; i++) acc[i] = fmaf(as[tg * 10 + i][jj], vv, acc[i]);
        }
        __syncthreads();
    }
    #pragma unroll
    for (int i = 0; i < 10; i++)
        atomicAdd(&g_upd[((size_t)(bh * NTOP) + tg * 10 + i) * Dd + td], acc[i]);
}

// ================= 8-10) base / broadcast / corrections =================
__global__ void __launch_bounds__(256) base_kernel(const float* __restrict__ Wo, const float* __restrict__ bo) {
    int b = blockIdx.x;
    __shared__ float cm[Es];
    int tid = threadIdx.x;
    cm[tid] = g_vmean[b * Es + tid];
    cm[tid + 256] = g_vmean[b * Es + 256 + tid];
    __syncthreads();
    for (int r = 0; r < 2; r++) {
        int e = r * 256 + tid;
        const float4* wr = (const float4*)(Wo + (size_t)e * Es);
        float acc = bo[e];
        for (int c4 = 0; c4 < Es / 4; c4++) {
            float4 w = wr[c4];
            acc += cm[4*c4] * w.x + cm[4*c4+1] * w.y + cm[4*c4+2] * w.z + cm[4*c4+3] * w.w;
        }
        g_base[b * Es + e] = acc;
    }
}

__global__ void broadcast_kernel(float4* __restrict__ out) {
    int idx = blockIdx.x * blockDim.x + threadIdx.x;
    if (idx < Bb * Ls * Es / 4) {
        int per_b = Ls * Es / 4;
        int b = idx / per_b;
        int e4 = idx & (Es / 4 - 1);
        out[idx] = ((const float4*)g_base)[b * (Es / 4) + e4];
    }
}

__global__ void __launch_bounds__(128) corr_kernel(const float* __restrict__ Wo, float* __restrict__ out) {
    int g = blockIdx.x;
    int bh = g / NTOP;
    int b = bh / Hh, h = bh % Hh;
    int l = g_top[g];
    __shared__ float delta[Dd];
    int tid = threadIdx.x;
    if (tid < Dd) delta[tid] = g_upd[(size_t)g * Dd + tid] - g_vmean[bh * Dd + tid];
    __syncthreads();
    float* orow = out + (size_t)(b * Ls + l) * Es;
    for (int r = 0; r < 4; r++) {
        int e = r * 128 + tid;
        const float4* wr = (const float4*)(Wo + (size_t)e * Es + h * Dd);
        float acc = 0.f;
        #pragma unroll
        for (int q = 0; q < 16; q++) {
            float4 w = wr[q];
            acc += delta[4*q] * w.x + delta[4*q+1] * w.y + delta[4*q+2] * w.z + delta[4*q+3] * w.w;
        }
        atomicAdd(orow + e, acc);
    }
}

// ================= launch =================
extern "C" void kernel_launch(void* const* d_in, const int* in_sizes, int n_in,
                              void* d_out, int out_size) {
    const float* query = (const float*)d_in[0];
    const float* key   = (const float*)d_in[1];
    const float* value = (const float*)d_in[2];
    const int*   idx   = (const int*)d_in[3];
    const float* Wq = (const float*)d_in[4];  const float* bq = (const float*)d_in[5];
    const float* Wk = (const float*)d_in[6];  const float* bk = (const float*)d_in[7];
    const float* Wv = (const float*)d_in[8];  const float* bv = (const float*)d_in[9];
    const float* Wo = (const float*)d_in[10]; const float* bo = (const float*)d_in[11];
    float* out = (float*)d_out;

    cvt_inputs<<<dim3(4096, 1, 3), 256>>>(query, key, value);
    cvt_weights<<<dim3(256, 1, 3), 256>>>(Wq, Wk, Wv);

    colmean_kernel<<<dim3(8, Bb), 256>>>(value);
    vmean_gemm<<<Bb, 256>>>(Wv, bv);

    cudaFuncSetAttribute(proj_mma, cudaFuncAttributeMaxDynamicSharedMemorySize, SM_TOT);
    cudaFuncSetAttribute(proj_v, cudaFuncAttributeMaxDynamicSharedMemorySize, SM_TOT);
    proj_mma<<<dim3(4, 64, 2), 256, SM_TOT>>>(bq, bk);
    proj_v<<<dim3(4, 64), 256, SM_TOT>>>(bv);

    m_kernel<<<dim3(Ls / 8, BH), 256>>>(idx);
    topk_kernel<<<BH, 256>>>();

    scores_kernel<<<dim3(16, BH), 256>>>();
    softmax_kernel<<<BH * NTOP, 256>>>();
    upd_kernel<<<dim3(8, BH), 256>>>();

    base_kernel<<<Bb, 256>>>(Wo, bo);
    broadcast_kernel<<<(Bb * Ls * Es / 4 + 255) / 256, 256>>>((float4*)out);
    corr_kernel<<<BH * NTOP, 128>>>(Wo, out);
}